// round 3
// baseline (speedup 1.0000x reference)
#include <cuda_runtime.h>

#define DIM   96
#define DIM3  (DIM * DIM * DIM)   // 884736
#define CH    24
#define CH4   (CH / 4)            // 6 float4 per voxel row

// ---------------- scratch (device globals; no allocation allowed) ----------------
__device__ int           g_win_cur[DIM3];
__device__ int           g_win_glb[DIM3];
__device__ int           g_win_tgt[DIM3];
__device__ unsigned char g_valid_vol[DIM3];
__device__ unsigned char g_occ[DIM3];

// ---------------- kernels ----------------

__global__ void k_init() {
    int i = blockIdx.x * blockDim.x + threadIdx.x;
    if (i < DIM3) {
        g_win_cur[i]   = -1;
        g_win_glb[i]   = -1;
        g_win_tgt[i]   = -1;
        g_valid_vol[i] = 0;
        g_occ[i]       = 0;
    }
}

// Scatter current fragment rows:
//  - valid_volume[voxel] |= grid_mask[i]
//  - occ_volume[voxel]   |= occupancy[i]
//  - winner_cur[voxel]    = max(row)  (== sequential last-write-wins of XLA scatter)
// Masks are 4-byte (bool promoted to int32 or float32 by the harness);
// `!= 0` is correct for both representations.
__global__ void k_scatter_cur(const int* __restrict__ cc,
                              const int* __restrict__ gm,
                              const int* __restrict__ occ,
                              int n) {
    int i = blockIdx.x * blockDim.x + threadIdx.x;
    if (i >= n) return;
    int x = cc[3 * i], y = cc[3 * i + 1], z = cc[3 * i + 2];
    int v = (x * DIM + y) * DIM + z;
    atomicMax(&g_win_cur[v], i);
    if (gm[i] != 0)  g_valid_vol[v] = 1;
    if (occ[i] != 0) g_occ[v] = 1;
}

// Global rows: shift by origin, in-bounds test, gather valid_volume,
// emit `valid` and `near_mask`, record winner for global_volume.
__global__ void k_scatter_glb(const int* __restrict__ gc,
                              const int* __restrict__ origin,
                              float* __restrict__ out_valid,
                              float* __restrict__ out_near,
                              int n) {
    int i = blockIdx.x * blockDim.x + threadIdx.x;
    if (i >= n) return;
    int x = gc[3 * i]     - origin[0];
    int y = gc[3 * i + 1] - origin[1];
    int z = gc[3 * i + 2] - origin[2];
    bool inb = ((unsigned)x < DIM) && ((unsigned)y < DIM) && ((unsigned)z < DIM);
    bool valid = false;
    if (inb) {
        int v = (x * DIM + y) * DIM + z;
        valid = (g_valid_vol[v] != 0);
        if (valid) atomicMax(&g_win_glb[v], i);
    }
    out_valid[i] = valid ? 1.0f : 0.0f;
    out_near[i]  = (inb && !valid) ? 1.0f : 0.0f;
}

// Target scatters. Global target rows scattered first (priority = row),
// current-fragment target rows second (priority = n_g + row) so they win,
// atomicMax reproduces sequential last-write-wins within each set.
__global__ void k_scatter_tgt(const int* __restrict__ gct,
                              const int* __restrict__ origin,
                              const int* __restrict__ ct,
                              float* __restrict__ out_vt,
                              int n_g, int n_c) {
    int i = blockIdx.x * blockDim.x + threadIdx.x;
    if (i < n_g) {
        int x = gct[3 * i]     - origin[0];
        int y = gct[3 * i + 1] - origin[1];
        int z = gct[3 * i + 2] - origin[2];
        bool inb = ((unsigned)x < DIM) && ((unsigned)y < DIM) && ((unsigned)z < DIM);
        out_vt[i] = inb ? 1.0f : 0.0f;
        if (inb) {
            int v = (x * DIM + y) * DIM + z;
            atomicMax(&g_win_tgt[v], i);
        }
    } else if (i < n_g + n_c) {
        int t = i - n_g;
        int x = ct[3 * t], y = ct[3 * t + 1], z = ct[3 * t + 2];
        int v = (x * DIM + y) * DIM + z;
        atomicMax(&g_win_tgt[v], n_g + t);
    }
}

// Dense fill of both 96^3 x 24 feature volumes at float4 granularity
// (24 ch = 6 float4; rows are 96B so 16B-aligned). Streaming coalesced stores,
// winner index shared by 6 consecutive threads (L1 broadcast), value-table
// gathers hit L2 (tables are 14/29 MB, L2 is 126 MB).
__global__ void k_fill_feat(const float4* __restrict__ cur_vals,
                            const float4* __restrict__ glb_vals,
                            float4* __restrict__ out_cur,
                            float4* __restrict__ out_glb) {
    int e = blockIdx.x * blockDim.x + threadIdx.x;   // float4 index
    if (e >= DIM3 * CH4) return;
    int v = e / CH4;
    int q = e - v * CH4;
    const float4 zero = make_float4(0.f, 0.f, 0.f, 0.f);
    int wc = g_win_cur[v];
    out_cur[e] = (wc >= 0) ? cur_vals[wc * CH4 + q] : zero;
    int wg = g_win_glb[v];
    out_glb[e] = (wg >= 0) ? glb_vals[wg * CH4 + q] : zero;
}

// target_volume (default 1.0) + updated_mask = (global_volume != 0).any(-1) | occ
__global__ void k_fill_misc(const float* __restrict__ glb_vals,
                            const float* __restrict__ tsdf_tgt,
                            const float* __restrict__ gtsdf_tgt,
                            float* __restrict__ out_tgt,
                            float* __restrict__ out_mask,
                            int n_gtgt) {
    int v = blockIdx.x * blockDim.x + threadIdx.x;
    if (v >= DIM3) return;

    int wt = g_win_tgt[v];
    float t;
    if (wt < 0)            t = 1.0f;
    else if (wt >= n_gtgt) t = tsdf_tgt[wt - n_gtgt];
    else                   t = gtsdf_tgt[wt];
    out_tgt[v] = t;

    bool m = (g_occ[v] != 0);
    int wg = g_win_glb[v];
    if (!m && wg >= 0) {
        const float* r = &glb_vals[wg * CH];
        bool nz = false;
        #pragma unroll
        for (int c = 0; c < CH; ++c) nz |= (r[c] != 0.0f);
        m = nz;
    }
    out_mask[v] = m ? 1.0f : 0.0f;
}

// ---------------- launch ----------------

extern "C" void kernel_launch(void* const* d_in, const int* in_sizes, int n_in,
                              void* d_out, int out_size) {
    const int*   cur_coords = (const int*)d_in[0];
    const float* cur_vals   = (const float*)d_in[1];
    const int*   glb_coords = (const int*)d_in[2];
    const float* glb_vals   = (const float*)d_in[3];
    const int*   ct_coords  = (const int*)d_in[4];
    const float* tsdf_tgt   = (const float*)d_in[5];
    const int*   gct_coords = (const int*)d_in[6];
    const float* gtsdf_tgt  = (const float*)d_in[7];
    const int*   origin     = (const int*)d_in[8];
    const int*   grid_mask  = (const int*)d_in[9];   // bool promoted to 4-byte
    const int*   occupancy  = (const int*)d_in[10];  // bool promoted to 4-byte

    const int n_cur  = in_sizes[0] / 3;
    const int n_glb  = in_sizes[2] / 3;
    const int n_tgt  = in_sizes[4] / 3;
    const int n_gtgt = in_sizes[6] / 3;

    float* out = (float*)d_out;
    // output layout: tuple order, flattened, float32
    float* out_mask  = out;                          // DIM3
    float* out_cur   = out_mask + DIM3;              // DIM3*CH
    float* out_glb   = out_cur + (size_t)DIM3 * CH;  // DIM3*CH
    float* out_tgt   = out_glb + (size_t)DIM3 * CH;  // DIM3
    float* out_valid = out_tgt + DIM3;               // n_glb
    float* out_vt    = out_valid + n_glb;            // n_gtgt
    float* out_near  = out_vt + n_gtgt;              // n_glb

    const int B = 256;

    k_init<<<(DIM3 + B - 1) / B, B>>>();
    k_scatter_cur<<<(n_cur + B - 1) / B, B>>>(cur_coords, grid_mask, occupancy, n_cur);
    k_scatter_glb<<<(n_glb + B - 1) / B, B>>>(glb_coords, origin, out_valid, out_near, n_glb);
    k_scatter_tgt<<<(n_gtgt + n_tgt + B - 1) / B, B>>>(gct_coords, origin, ct_coords,
                                                       out_vt, n_gtgt, n_tgt);
    k_fill_feat<<<(DIM3 * CH4 + B - 1) / B, B>>>((const float4*)cur_vals, (const float4*)glb_vals,
                                                 (float4*)out_cur, (float4*)out_glb);
    k_fill_misc<<<(DIM3 + B - 1) / B, B>>>(glb_vals, tsdf_tgt, gtsdf_tgt,
                                           out_tgt, out_mask, n_gtgt);
}

// round 4
// speedup vs baseline: 1.0619x; 1.0619x over previous
#include <cuda_runtime.h>

#define DIM   96
#define DIM3  (DIM * DIM * DIM)   // 884736
#define CH    24
#define CH4   (CH / 4)            // 6 float4 per voxel row
#define FEAT4 (DIM3 * CH4)        // 5308416 float4 elements per volume

// ---------------- scratch (device globals; no allocation allowed) ----------------
__device__ int           g_win_cur[DIM3];
__device__ int           g_win_glb[DIM3];   // packed: (row << 1) | row_has_nonzero
__device__ int           g_win_tgt[DIM3];
__device__ unsigned char g_valid_vol[DIM3];
__device__ unsigned char g_occ[DIM3];

// ---------------- kernels ----------------

// Vectorized scratch reset: winners = -1 (int4), flags = 0 (uchar4-as-int).
__global__ void k_init() {
    int i = blockIdx.x * blockDim.x + threadIdx.x;
    if (i < DIM3 / 4) {
        const int4 m1 = make_int4(-1, -1, -1, -1);
        ((int4*)g_win_cur)[i] = m1;
        ((int4*)g_win_glb)[i] = m1;
        ((int4*)g_win_tgt)[i] = m1;
        ((int*)g_valid_vol)[i] = 0;
        ((int*)g_occ)[i] = 0;
    }
}

// Fused: current-fragment scatter (range [0, n_cur)) and target scatters
// (range [n_cur, n_cur + n_gtgt + n_tgt)). Independent work, one launch.
// atomicMax(row-priority) reproduces XLA's sequential last-write-wins.
__global__ void k_scatter_a(const int* __restrict__ cc,
                            const int* __restrict__ gm,
                            const int* __restrict__ occ,
                            const int* __restrict__ gct,
                            const int* __restrict__ ct,
                            const int* __restrict__ origin,
                            float* __restrict__ out_vt,
                            int n_cur, int n_g, int n_c) {
    int i = blockIdx.x * blockDim.x + threadIdx.x;
    if (i < n_cur) {
        int x = cc[3 * i], y = cc[3 * i + 1], z = cc[3 * i + 2];
        int v = (x * DIM + y) * DIM + z;
        atomicMax(&g_win_cur[v], i);
        if (gm[i] != 0)  g_valid_vol[v] = 1;
        if (occ[i] != 0) g_occ[v] = 1;
        return;
    }
    int j = i - n_cur;
    if (j < n_g) {
        // global target rows: scattered first -> lower priority band [0, n_g)
        int x = gct[3 * j]     - origin[0];
        int y = gct[3 * j + 1] - origin[1];
        int z = gct[3 * j + 2] - origin[2];
        bool inb = ((unsigned)x < DIM) && ((unsigned)y < DIM) && ((unsigned)z < DIM);
        out_vt[j] = inb ? 1.0f : 0.0f;
        if (inb) atomicMax(&g_win_tgt[(x * DIM + y) * DIM + z], j);
    } else if (j < n_g + n_c) {
        // current-fragment target rows: scattered second -> win ties, band [n_g, n_g+n_c)
        int t = j - n_g;
        int x = ct[3 * t], y = ct[3 * t + 1], z = ct[3 * t + 2];
        atomicMax(&g_win_tgt[(x * DIM + y) * DIM + z], n_g + t);
    }
}

// Global rows: shift by origin, in-bounds test, gather valid_volume,
// emit `valid`/`near_mask`, record packed winner (row<<1 | row_any_nonzero).
// The nz bit lets the fill stage compute updated_mask without re-gathering
// the 24-float row; the sequential row read here also pre-warms L2.
__global__ void k_scatter_glb(const int* __restrict__ gc,
                              const float4* __restrict__ glb_vals,
                              const int* __restrict__ origin,
                              float* __restrict__ out_valid,
                              float* __restrict__ out_near,
                              int n) {
    int i = blockIdx.x * blockDim.x + threadIdx.x;
    if (i >= n) return;
    int x = gc[3 * i]     - origin[0];
    int y = gc[3 * i + 1] - origin[1];
    int z = gc[3 * i + 2] - origin[2];
    bool inb = ((unsigned)x < DIM) && ((unsigned)y < DIM) && ((unsigned)z < DIM);
    bool valid = false;
    if (inb) {
        int v = (x * DIM + y) * DIM + z;
        valid = (g_valid_vol[v] != 0);
        if (valid) {
            bool nz = false;
            #pragma unroll
            for (int q = 0; q < CH4; ++q) {
                float4 r = glb_vals[i * CH4 + q];
                nz |= (r.x != 0.0f) | (r.y != 0.0f) | (r.z != 0.0f) | (r.w != 0.0f);
            }
            atomicMax(&g_win_glb[v], (i << 1) | (nz ? 1 : 0));
        }
    }
    out_valid[i] = valid ? 1.0f : 0.0f;
    out_near[i]  = (inb && !valid) ? 1.0f : 0.0f;
}

// Fused dense fill. Range [0, FEAT4): both feature volumes at float4
// granularity (coalesced streaming stores, value gathers hit L2).
// Range [FEAT4, FEAT4 + DIM3): target_volume + updated_mask.
__global__ void k_fill(const float4* __restrict__ cur_vals,
                       const float4* __restrict__ glb_vals,
                       const float* __restrict__ tsdf_tgt,
                       const float* __restrict__ gtsdf_tgt,
                       float4* __restrict__ out_cur,
                       float4* __restrict__ out_glb,
                       float* __restrict__ out_tgt,
                       float* __restrict__ out_mask,
                       int n_gtgt) {
    int e = blockIdx.x * blockDim.x + threadIdx.x;
    if (e < FEAT4) {
        int v = e / CH4;
        int q = e - v * CH4;
        const float4 zero = make_float4(0.f, 0.f, 0.f, 0.f);
        int wc = g_win_cur[v];
        out_cur[e] = (wc >= 0) ? cur_vals[wc * CH4 + q] : zero;
        int wg = g_win_glb[v];
        out_glb[e] = (wg >= 0) ? glb_vals[(wg >> 1) * CH4 + q] : zero;
        return;
    }
    int v = e - FEAT4;
    if (v >= DIM3) return;

    int wt = g_win_tgt[v];
    float t;
    if (wt < 0)            t = 1.0f;
    else if (wt >= n_gtgt) t = tsdf_tgt[wt - n_gtgt];
    else                   t = gtsdf_tgt[wt];
    out_tgt[v] = t;

    int wg = g_win_glb[v];
    bool m = (g_occ[v] != 0) | (wg >= 0 && (wg & 1));
    out_mask[v] = m ? 1.0f : 0.0f;
}

// ---------------- launch ----------------

extern "C" void kernel_launch(void* const* d_in, const int* in_sizes, int n_in,
                              void* d_out, int out_size) {
    const int*   cur_coords = (const int*)d_in[0];
    const float* cur_vals   = (const float*)d_in[1];
    const int*   glb_coords = (const int*)d_in[2];
    const float* glb_vals   = (const float*)d_in[3];
    const int*   ct_coords  = (const int*)d_in[4];
    const float* tsdf_tgt   = (const float*)d_in[5];
    const int*   gct_coords = (const int*)d_in[6];
    const float* gtsdf_tgt  = (const float*)d_in[7];
    const int*   origin     = (const int*)d_in[8];
    const int*   grid_mask  = (const int*)d_in[9];   // bool promoted to 4-byte
    const int*   occupancy  = (const int*)d_in[10];  // bool promoted to 4-byte

    const int n_cur  = in_sizes[0] / 3;
    const int n_glb  = in_sizes[2] / 3;
    const int n_tgt  = in_sizes[4] / 3;
    const int n_gtgt = in_sizes[6] / 3;

    float* out = (float*)d_out;
    // output layout: tuple order, flattened, float32
    float* out_mask  = out;                          // DIM3
    float* out_cur   = out_mask + DIM3;              // DIM3*CH
    float* out_glb   = out_cur + (size_t)DIM3 * CH;  // DIM3*CH
    float* out_tgt   = out_glb + (size_t)DIM3 * CH;  // DIM3
    float* out_valid = out_tgt + DIM3;               // n_glb
    float* out_vt    = out_valid + n_glb;            // n_gtgt
    float* out_near  = out_vt + n_gtgt;              // n_glb

    const int B = 256;

    k_init<<<(DIM3 / 4 + B - 1) / B, B>>>();

    int n_a = n_cur + n_gtgt + n_tgt;
    k_scatter_a<<<(n_a + B - 1) / B, B>>>(cur_coords, grid_mask, occupancy,
                                          gct_coords, ct_coords, origin,
                                          out_vt, n_cur, n_gtgt, n_tgt);

    k_scatter_glb<<<(n_glb + B - 1) / B, B>>>(glb_coords, (const float4*)glb_vals,
                                              origin, out_valid, out_near, n_glb);

    int n_f = FEAT4 + DIM3;
    k_fill<<<(n_f + B - 1) / B, B>>>((const float4*)cur_vals, (const float4*)glb_vals,
                                     tsdf_tgt, gtsdf_tgt,
                                     (float4*)out_cur, (float4*)out_glb,
                                     out_tgt, out_mask, n_gtgt);
}

// round 5
// speedup vs baseline: 1.1585x; 1.0910x over previous
#include <cuda_runtime.h>

#define DIM   96
#define DIM3  (DIM * DIM * DIM)   // 884736
#define CH    24
#define CH4   (CH / 4)            // 6 float4 per voxel row
#define FEAT4 (DIM3 * CH4)        // 5308416 float4 elements per volume

#define B         256
#define FILL_ILP  4
#define FILL_THREADS (FEAT4 / FILL_ILP)          // 1327104 (exact)
#define FILL_BLOCKS  (FILL_THREADS / B)          // 5184 (exact)
#define MISC_BLOCKS  ((DIM3 + B - 1) / B)        // 3456

// ---------------- scratch (device globals; no allocation allowed) ----------------
__device__ int           g_win_cur[DIM3];
__device__ int           g_win_glb[DIM3];   // packed: (row << 1) | row_has_nonzero
__device__ int           g_win_tgt[DIM3];
__device__ unsigned char g_valid_vol[DIM3];
__device__ unsigned char g_occ[DIM3];

// ---------------- kernels ----------------

// Vectorized scratch reset: winners = -1 (int4), flags = 0.
__global__ void k_init() {
    int i = blockIdx.x * blockDim.x + threadIdx.x;
    if (i < DIM3 / 4) {
        const int4 m1 = make_int4(-1, -1, -1, -1);
        ((int4*)g_win_cur)[i] = m1;
        ((int4*)g_win_glb)[i] = m1;
        ((int4*)g_win_tgt)[i] = m1;
        ((int*)g_valid_vol)[i] = 0;
        ((int*)g_occ)[i] = 0;
    }
}

// Fused: current-fragment scatter (range [0, n_cur)) and target scatters
// (range [n_cur, n_cur + n_gtgt + n_tgt)). Independent work, one launch.
// atomicMax(row-priority) reproduces XLA's sequential last-write-wins.
__global__ void k_scatter_a(const int* __restrict__ cc,
                            const int* __restrict__ gm,
                            const int* __restrict__ occ,
                            const int* __restrict__ gct,
                            const int* __restrict__ ct,
                            const int* __restrict__ origin,
                            float* __restrict__ out_vt,
                            int n_cur, int n_g, int n_c) {
    int i = blockIdx.x * blockDim.x + threadIdx.x;
    if (i < n_cur) {
        int x = cc[3 * i], y = cc[3 * i + 1], z = cc[3 * i + 2];
        int v = (x * DIM + y) * DIM + z;
        atomicMax(&g_win_cur[v], i);
        if (gm[i] != 0)  g_valid_vol[v] = 1;
        if (occ[i] != 0) g_occ[v] = 1;
        return;
    }
    int j = i - n_cur;
    if (j < n_g) {
        // global target rows: scattered first -> lower priority band [0, n_g)
        int x = gct[3 * j]     - origin[0];
        int y = gct[3 * j + 1] - origin[1];
        int z = gct[3 * j + 2] - origin[2];
        bool inb = ((unsigned)x < DIM) && ((unsigned)y < DIM) && ((unsigned)z < DIM);
        out_vt[j] = inb ? 1.0f : 0.0f;
        if (inb) atomicMax(&g_win_tgt[(x * DIM + y) * DIM + z], j);
    } else if (j < n_g + n_c) {
        // current-fragment target rows: scattered second -> win ties
        int t = j - n_g;
        int x = ct[3 * t], y = ct[3 * t + 1], z = ct[3 * t + 2];
        atomicMax(&g_win_tgt[(x * DIM + y) * DIM + z], n_g + t);
    }
}

// Global rows: shift by origin, in-bounds test, gather valid_volume,
// emit `valid`/`near_mask`, record packed winner (row<<1 | row_any_nonzero).
__global__ void k_scatter_glb(const int* __restrict__ gc,
                              const float4* __restrict__ glb_vals,
                              const int* __restrict__ origin,
                              float* __restrict__ out_valid,
                              float* __restrict__ out_near,
                              int n) {
    int i = blockIdx.x * blockDim.x + threadIdx.x;
    if (i >= n) return;
    int x = gc[3 * i]     - origin[0];
    int y = gc[3 * i + 1] - origin[1];
    int z = gc[3 * i + 2] - origin[2];
    bool inb = ((unsigned)x < DIM) && ((unsigned)y < DIM) && ((unsigned)z < DIM);
    bool valid = false;
    if (inb) {
        int v = (x * DIM + y) * DIM + z;
        valid = (g_valid_vol[v] != 0);
        if (valid) {
            bool nz = false;
            #pragma unroll
            for (int q = 0; q < CH4; ++q) {
                float4 r = glb_vals[i * CH4 + q];
                nz |= (r.x != 0.0f) | (r.y != 0.0f) | (r.z != 0.0f) | (r.w != 0.0f);
            }
            atomicMax(&g_win_glb[v], (i << 1) | (nz ? 1 : 0));
        }
    }
    out_valid[i] = valid ? 1.0f : 0.0f;
    out_near[i]  = (inb && !valid) ? 1.0f : 0.0f;
}

// Fused dense fill with 4-way ILP. First FILL_BLOCKS blocks: both feature
// volumes, each thread handling 4 grid-strided float4 elements (independent
// winner->gather->store chains => 4x MLP, fully coalesced per iteration).
// Remaining MISC_BLOCKS blocks: target_volume + updated_mask.
__global__ void k_fill(const float4* __restrict__ cur_vals,
                       const float4* __restrict__ glb_vals,
                       const float* __restrict__ tsdf_tgt,
                       const float* __restrict__ gtsdf_tgt,
                       float4* __restrict__ out_cur,
                       float4* __restrict__ out_glb,
                       float* __restrict__ out_tgt,
                       float* __restrict__ out_mask,
                       int n_gtgt) {
    int b = blockIdx.x;
    if (b < FILL_BLOCKS) {
        int base = b * B + threadIdx.x;
        const float4 zero = make_float4(0.f, 0.f, 0.f, 0.f);
        int e[FILL_ILP], wc[FILL_ILP], wg[FILL_ILP];
        #pragma unroll
        for (int k = 0; k < FILL_ILP; ++k) {
            e[k] = base + k * FILL_THREADS;
            int v = e[k] / CH4;
            wc[k] = g_win_cur[v];
            wg[k] = g_win_glb[v];
        }
        float4 rc[FILL_ILP], rg[FILL_ILP];
        #pragma unroll
        for (int k = 0; k < FILL_ILP; ++k) {
            int v = e[k] / CH4;
            int q = e[k] - v * CH4;
            rc[k] = (wc[k] >= 0) ? cur_vals[wc[k] * CH4 + q] : zero;
            rg[k] = (wg[k] >= 0) ? glb_vals[(wg[k] >> 1) * CH4 + q] : zero;
        }
        #pragma unroll
        for (int k = 0; k < FILL_ILP; ++k) {
            out_cur[e[k]] = rc[k];
            out_glb[e[k]] = rg[k];
        }
        return;
    }
    int v = (b - FILL_BLOCKS) * B + threadIdx.x;
    if (v >= DIM3) return;

    int wt = g_win_tgt[v];
    float t;
    if (wt < 0)            t = 1.0f;
    else if (wt >= n_gtgt) t = tsdf_tgt[wt - n_gtgt];
    else                   t = gtsdf_tgt[wt];
    out_tgt[v] = t;

    int wg = g_win_glb[v];
    bool m = (g_occ[v] != 0) | (wg >= 0 && (wg & 1));
    out_mask[v] = m ? 1.0f : 0.0f;
}

// ---------------- launch ----------------

extern "C" void kernel_launch(void* const* d_in, const int* in_sizes, int n_in,
                              void* d_out, int out_size) {
    const int*   cur_coords = (const int*)d_in[0];
    const float* cur_vals   = (const float*)d_in[1];
    const int*   glb_coords = (const int*)d_in[2];
    const float* glb_vals   = (const float*)d_in[3];
    const int*   ct_coords  = (const int*)d_in[4];
    const float* tsdf_tgt   = (const float*)d_in[5];
    const int*   gct_coords = (const int*)d_in[6];
    const float* gtsdf_tgt  = (const float*)d_in[7];
    const int*   origin     = (const int*)d_in[8];
    const int*   grid_mask  = (const int*)d_in[9];   // bool promoted to 4-byte
    const int*   occupancy  = (const int*)d_in[10];  // bool promoted to 4-byte

    const int n_cur  = in_sizes[0] / 3;
    const int n_glb  = in_sizes[2] / 3;
    const int n_tgt  = in_sizes[4] / 3;
    const int n_gtgt = in_sizes[6] / 3;

    float* out = (float*)d_out;
    // output layout: tuple order, flattened, float32
    float* out_mask  = out;                          // DIM3
    float* out_cur   = out_mask + DIM3;              // DIM3*CH
    float* out_glb   = out_cur + (size_t)DIM3 * CH;  // DIM3*CH
    float* out_tgt   = out_glb + (size_t)DIM3 * CH;  // DIM3
    float* out_valid = out_tgt + DIM3;               // n_glb
    float* out_vt    = out_valid + n_glb;            // n_gtgt
    float* out_near  = out_vt + n_gtgt;              // n_glb

    k_init<<<(DIM3 / 4 + B - 1) / B, B>>>();

    int n_a = n_cur + n_gtgt + n_tgt;
    k_scatter_a<<<(n_a + B - 1) / B, B>>>(cur_coords, grid_mask, occupancy,
                                          gct_coords, ct_coords, origin,
                                          out_vt, n_cur, n_gtgt, n_tgt);

    k_scatter_glb<<<(n_glb + B - 1) / B, B>>>(glb_coords, (const float4*)glb_vals,
                                              origin, out_valid, out_near, n_glb);

    k_fill<<<FILL_BLOCKS + MISC_BLOCKS, B>>>((const float4*)cur_vals, (const float4*)glb_vals,
                                             tsdf_tgt, gtsdf_tgt,
                                             (float4*)out_cur, (float4*)out_glb,
                                             out_tgt, out_mask, n_gtgt);
}

// round 6
// speedup vs baseline: 1.2149x; 1.0487x over previous
#include <cuda_runtime.h>

#define DIM   96
#define DIM3  (DIM * DIM * DIM)   // 884736
#define CH    24
#define CH4   (CH / 4)            // 6 float4 per voxel row
#define FEAT4 (DIM3 * CH4)        // 5308416 float4 elements per volume

#define B         256
#define FILL_ILP  8
#define FILL_THREADS (FEAT4 / FILL_ILP)          // 663552 (exact)
#define FILL_BLOCKS  (FILL_THREADS / B)          // 2592 (exact)
#define MISC_BLOCKS  ((DIM3 + B - 1) / B)        // 3456

// ---------------- scratch (device globals; no allocation allowed) ----------------
__device__ int           g_win_cur[DIM3];
__device__ int           g_win_glb[DIM3];   // packed: (row << 1) | row_has_nonzero
__device__ int           g_win_tgt[DIM3];
__device__ unsigned char g_valid_vol[DIM3];
__device__ unsigned char g_occ[DIM3];

// ---------------- kernels ----------------

// Vectorized scratch reset: winners = -1 (int4), flags = 0.
__global__ void k_init() {
    int i = blockIdx.x * blockDim.x + threadIdx.x;
    if (i < DIM3 / 4) {
        const int4 m1 = make_int4(-1, -1, -1, -1);
        ((int4*)g_win_cur)[i] = m1;
        ((int4*)g_win_glb)[i] = m1;
        ((int4*)g_win_tgt)[i] = m1;
        ((int*)g_valid_vol)[i] = 0;
        ((int*)g_occ)[i] = 0;
    }
}

// Fused: current-fragment scatter (range [0, n_cur)) and target scatters
// (range [n_cur, n_cur + n_gtgt + n_tgt)). Independent work, one launch.
// atomicMax(row-priority) reproduces XLA's sequential last-write-wins.
__global__ void k_scatter_a(const int* __restrict__ cc,
                            const int* __restrict__ gm,
                            const int* __restrict__ occ,
                            const int* __restrict__ gct,
                            const int* __restrict__ ct,
                            const int* __restrict__ origin,
                            float* __restrict__ out_vt,
                            int n_cur, int n_g, int n_c) {
    int i = blockIdx.x * blockDim.x + threadIdx.x;
    if (i < n_cur) {
        int x = cc[3 * i], y = cc[3 * i + 1], z = cc[3 * i + 2];
        int v = (x * DIM + y) * DIM + z;
        atomicMax(&g_win_cur[v], i);
        if (gm[i] != 0)  g_valid_vol[v] = 1;
        if (occ[i] != 0) g_occ[v] = 1;
        return;
    }
    int j = i - n_cur;
    if (j < n_g) {
        // global target rows: scattered first -> lower priority band [0, n_g)
        int x = gct[3 * j]     - origin[0];
        int y = gct[3 * j + 1] - origin[1];
        int z = gct[3 * j + 2] - origin[2];
        bool inb = ((unsigned)x < DIM) && ((unsigned)y < DIM) && ((unsigned)z < DIM);
        out_vt[j] = inb ? 1.0f : 0.0f;
        if (inb) atomicMax(&g_win_tgt[(x * DIM + y) * DIM + z], j);
    } else if (j < n_g + n_c) {
        // current-fragment target rows: scattered second -> win ties
        int t = j - n_g;
        int x = ct[3 * t], y = ct[3 * t + 1], z = ct[3 * t + 2];
        atomicMax(&g_win_tgt[(x * DIM + y) * DIM + z], n_g + t);
    }
}

// Global rows: shift by origin, in-bounds test, gather valid_volume,
// emit `valid`/`near_mask`, record packed winner (row<<1 | row_any_nonzero).
__global__ void k_scatter_glb(const int* __restrict__ gc,
                              const float4* __restrict__ glb_vals,
                              const int* __restrict__ origin,
                              float* __restrict__ out_valid,
                              float* __restrict__ out_near,
                              int n) {
    int i = blockIdx.x * blockDim.x + threadIdx.x;
    if (i >= n) return;
    int x = gc[3 * i]     - origin[0];
    int y = gc[3 * i + 1] - origin[1];
    int z = gc[3 * i + 2] - origin[2];
    bool inb = ((unsigned)x < DIM) && ((unsigned)y < DIM) && ((unsigned)z < DIM);
    bool valid = false;
    if (inb) {
        int v = (x * DIM + y) * DIM + z;
        valid = (g_valid_vol[v] != 0);
        if (valid) {
            bool nz = false;
            #pragma unroll
            for (int q = 0; q < CH4; ++q) {
                float4 r = glb_vals[i * CH4 + q];
                nz |= (r.x != 0.0f) | (r.y != 0.0f) | (r.z != 0.0f) | (r.w != 0.0f);
            }
            atomicMax(&g_win_glb[v], (i << 1) | (nz ? 1 : 0));
        }
    }
    out_valid[i] = valid ? 1.0f : 0.0f;
    out_near[i]  = (inb && !valid) ? 1.0f : 0.0f;
}

// Fused dense fill with 8-way ILP and streaming stores. First FILL_BLOCKS
// blocks: both feature volumes, each thread handling 8 grid-strided float4
// elements (independent winner->gather->store chains, fully coalesced per
// slice). __stcs on output writes keeps the value tables + winner arrays
// L2-resident instead of letting 177MB of write-once data thrash them.
// Remaining MISC_BLOCKS blocks: target_volume + updated_mask.
__global__ void k_fill(const float4* __restrict__ cur_vals,
                       const float4* __restrict__ glb_vals,
                       const float* __restrict__ tsdf_tgt,
                       const float* __restrict__ gtsdf_tgt,
                       float4* __restrict__ out_cur,
                       float4* __restrict__ out_glb,
                       float* __restrict__ out_tgt,
                       float* __restrict__ out_mask,
                       int n_gtgt) {
    int b = blockIdx.x;
    if (b < FILL_BLOCKS) {
        int base = b * B + threadIdx.x;
        const float4 zero = make_float4(0.f, 0.f, 0.f, 0.f);
        int e[FILL_ILP], wc[FILL_ILP], wg[FILL_ILP];
        #pragma unroll
        for (int k = 0; k < FILL_ILP; ++k) {
            e[k] = base + k * FILL_THREADS;
            int v = e[k] / CH4;
            wc[k] = g_win_cur[v];
            wg[k] = g_win_glb[v];
        }
        #pragma unroll
        for (int k = 0; k < FILL_ILP; ++k) {
            int v = e[k] / CH4;
            int q = e[k] - v * CH4;
            float4 rc = (wc[k] >= 0) ? cur_vals[wc[k] * CH4 + q] : zero;
            float4 rg = (wg[k] >= 0) ? glb_vals[(wg[k] >> 1) * CH4 + q] : zero;
            __stcs(&out_cur[e[k]], rc);
            __stcs(&out_glb[e[k]], rg);
        }
        return;
    }
    int v = (b - FILL_BLOCKS) * B + threadIdx.x;
    if (v >= DIM3) return;

    int wt = g_win_tgt[v];
    float t;
    if (wt < 0)            t = 1.0f;
    else if (wt >= n_gtgt) t = tsdf_tgt[wt - n_gtgt];
    else                   t = gtsdf_tgt[wt];
    __stcs(&out_tgt[v], t);

    int wg = g_win_glb[v];
    bool m = (g_occ[v] != 0) | (wg >= 0 && (wg & 1));
    __stcs(&out_mask[v], m ? 1.0f : 0.0f);
}

// ---------------- launch ----------------

extern "C" void kernel_launch(void* const* d_in, const int* in_sizes, int n_in,
                              void* d_out, int out_size) {
    const int*   cur_coords = (const int*)d_in[0];
    const float* cur_vals   = (const float*)d_in[1];
    const int*   glb_coords = (const int*)d_in[2];
    const float* glb_vals   = (const float*)d_in[3];
    const int*   ct_coords  = (const int*)d_in[4];
    const float* tsdf_tgt   = (const float*)d_in[5];
    const int*   gct_coords = (const int*)d_in[6];
    const float* gtsdf_tgt  = (const float*)d_in[7];
    const int*   origin     = (const int*)d_in[8];
    const int*   grid_mask  = (const int*)d_in[9];   // bool promoted to 4-byte
    const int*   occupancy  = (const int*)d_in[10];  // bool promoted to 4-byte

    const int n_cur  = in_sizes[0] / 3;
    const int n_glb  = in_sizes[2] / 3;
    const int n_tgt  = in_sizes[4] / 3;
    const int n_gtgt = in_sizes[6] / 3;

    float* out = (float*)d_out;
    // output layout: tuple order, flattened, float32
    float* out_mask  = out;                          // DIM3
    float* out_cur   = out_mask + DIM3;              // DIM3*CH
    float* out_glb   = out_cur + (size_t)DIM3 * CH;  // DIM3*CH
    float* out_tgt   = out_glb + (size_t)DIM3 * CH;  // DIM3
    float* out_valid = out_tgt + DIM3;               // n_glb
    float* out_vt    = out_valid + n_glb;            // n_gtgt
    float* out_near  = out_vt + n_gtgt;              // n_glb

    k_init<<<(DIM3 / 4 + B - 1) / B, B>>>();

    int n_a = n_cur + n_gtgt + n_tgt;
    k_scatter_a<<<(n_a + B - 1) / B, B>>>(cur_coords, grid_mask, occupancy,
                                          gct_coords, ct_coords, origin,
                                          out_vt, n_cur, n_gtgt, n_tgt);

    k_scatter_glb<<<(n_glb + B - 1) / B, B>>>(glb_coords, (const float4*)glb_vals,
                                              origin, out_valid, out_near, n_glb);

    k_fill<<<FILL_BLOCKS + MISC_BLOCKS, B>>>((const float4*)cur_vals, (const float4*)glb_vals,
                                             tsdf_tgt, gtsdf_tgt,
                                             (float4*)out_cur, (float4*)out_glb,
                                             out_tgt, out_mask, n_gtgt);
}

// round 7
// speedup vs baseline: 1.2213x; 1.0052x over previous
#include <cuda_runtime.h>

#define DIM   96
#define DIM3  (DIM * DIM * DIM)   // 884736
#define CH    24
#define CH4   (CH / 4)            // 6 float4 per voxel row
#define FEAT4 (DIM3 * CH4)        // 5308416 float4 elements per volume

#define B         256
#define FILL_ILP  4
#define FILL_THREADS (FEAT4 / FILL_ILP)          // 1327104 (exact)
#define FILL_BLOCKS  (FILL_THREADS / B)          // 5184 (exact)
#define MISC_BLOCKS  ((DIM3 + B - 1) / B)        // 3456

// ---------------- scratch (device globals; no allocation allowed) ----------------
__device__ int           g_win_cur[DIM3];
__device__ int           g_win_glb[DIM3];   // packed: (row << 1) | row_has_nonzero
__device__ int           g_win_tgt[DIM3];
__device__ unsigned char g_valid_vol[DIM3];
__device__ unsigned char g_occ[DIM3];

// ---------------- kernels ----------------

// Vectorized scratch reset: winners = -1 (int4), flags = 0.
__global__ void k_init() {
    int i = blockIdx.x * blockDim.x + threadIdx.x;
    if (i < DIM3 / 4) {
        const int4 m1 = make_int4(-1, -1, -1, -1);
        ((int4*)g_win_cur)[i] = m1;
        ((int4*)g_win_glb)[i] = m1;
        ((int4*)g_win_tgt)[i] = m1;
        ((int*)g_valid_vol)[i] = 0;
        ((int*)g_occ)[i] = 0;
    }
}

// Fused: current-fragment scatter (range [0, n_cur)) and target scatters
// (range [n_cur, n_cur + n_gtgt + n_tgt)). Independent work, one launch.
// atomicMax(row-priority) reproduces XLA's sequential last-write-wins.
__global__ void k_scatter_a(const int* __restrict__ cc,
                            const int* __restrict__ gm,
                            const int* __restrict__ occ,
                            const int* __restrict__ gct,
                            const int* __restrict__ ct,
                            const int* __restrict__ origin,
                            float* __restrict__ out_vt,
                            int n_cur, int n_g, int n_c) {
    int i = blockIdx.x * blockDim.x + threadIdx.x;
    if (i < n_cur) {
        int x = cc[3 * i], y = cc[3 * i + 1], z = cc[3 * i + 2];
        int v = (x * DIM + y) * DIM + z;
        atomicMax(&g_win_cur[v], i);
        if (gm[i] != 0)  g_valid_vol[v] = 1;
        if (occ[i] != 0) g_occ[v] = 1;
        return;
    }
    int j = i - n_cur;
    if (j < n_g) {
        // global target rows: scattered first -> lower priority band [0, n_g)
        int x = gct[3 * j]     - origin[0];
        int y = gct[3 * j + 1] - origin[1];
        int z = gct[3 * j + 2] - origin[2];
        bool inb = ((unsigned)x < DIM) && ((unsigned)y < DIM) && ((unsigned)z < DIM);
        out_vt[j] = inb ? 1.0f : 0.0f;
        if (inb) atomicMax(&g_win_tgt[(x * DIM + y) * DIM + z], j);
    } else if (j < n_g + n_c) {
        // current-fragment target rows: scattered second -> win ties
        int t = j - n_g;
        int x = ct[3 * t], y = ct[3 * t + 1], z = ct[3 * t + 2];
        atomicMax(&g_win_tgt[(x * DIM + y) * DIM + z], n_g + t);
    }
}

// Global rows: shift by origin, in-bounds test, gather valid_volume,
// emit `valid`/`near_mask`, record packed winner (row<<1 | row_any_nonzero).
__global__ void k_scatter_glb(const int* __restrict__ gc,
                              const float4* __restrict__ glb_vals,
                              const int* __restrict__ origin,
                              float* __restrict__ out_valid,
                              float* __restrict__ out_near,
                              int n) {
    int i = blockIdx.x * blockDim.x + threadIdx.x;
    if (i >= n) return;
    int x = gc[3 * i]     - origin[0];
    int y = gc[3 * i + 1] - origin[1];
    int z = gc[3 * i + 2] - origin[2];
    bool inb = ((unsigned)x < DIM) && ((unsigned)y < DIM) && ((unsigned)z < DIM);
    bool valid = false;
    if (inb) {
        int v = (x * DIM + y) * DIM + z;
        valid = (g_valid_vol[v] != 0);
        if (valid) {
            bool nz = false;
            #pragma unroll
            for (int q = 0; q < CH4; ++q) {
                float4 r = glb_vals[i * CH4 + q];
                nz |= (r.x != 0.0f) | (r.y != 0.0f) | (r.z != 0.0f) | (r.w != 0.0f);
            }
            atomicMax(&g_win_glb[v], (i << 1) | (nz ? 1 : 0));
        }
    }
    out_valid[i] = valid ? 1.0f : 0.0f;
    out_near[i]  = (inb && !valid) ? 1.0f : 0.0f;
}

// Fused dense fill. Misc blocks (target_volume + updated_mask) come FIRST in
// the grid so they don't trail as a ragged tail behind the heavy fill blocks.
// Fill blocks: 4-way ILP over grid-strided float4 slices (independent
// winner->gather->store chains, coalesced), __stcs streaming stores keep the
// value tables + winner arrays L2-resident (output is write-once).
__global__ void k_fill(const float4* __restrict__ cur_vals,
                       const float4* __restrict__ glb_vals,
                       const float* __restrict__ tsdf_tgt,
                       const float* __restrict__ gtsdf_tgt,
                       float4* __restrict__ out_cur,
                       float4* __restrict__ out_glb,
                       float* __restrict__ out_tgt,
                       float* __restrict__ out_mask,
                       int n_gtgt) {
    int b = blockIdx.x;
    if (b >= MISC_BLOCKS) {
        int base = (b - MISC_BLOCKS) * B + threadIdx.x;
        const float4 zero = make_float4(0.f, 0.f, 0.f, 0.f);
        int e[FILL_ILP], wc[FILL_ILP], wg[FILL_ILP];
        #pragma unroll
        for (int k = 0; k < FILL_ILP; ++k) {
            e[k] = base + k * FILL_THREADS;
            int v = e[k] / CH4;
            wc[k] = g_win_cur[v];
            wg[k] = g_win_glb[v];
        }
        #pragma unroll
        for (int k = 0; k < FILL_ILP; ++k) {
            int v = e[k] / CH4;
            int q = e[k] - v * CH4;
            float4 rc = (wc[k] >= 0) ? cur_vals[wc[k] * CH4 + q] : zero;
            float4 rg = (wg[k] >= 0) ? glb_vals[(wg[k] >> 1) * CH4 + q] : zero;
            __stcs(&out_cur[e[k]], rc);
            __stcs(&out_glb[e[k]], rg);
        }
        return;
    }
    int v = b * B + threadIdx.x;
    if (v >= DIM3) return;

    int wt = g_win_tgt[v];
    float t;
    if (wt < 0)            t = 1.0f;
    else if (wt >= n_gtgt) t = tsdf_tgt[wt - n_gtgt];
    else                   t = gtsdf_tgt[wt];
    __stcs(&out_tgt[v], t);

    int wg = g_win_glb[v];
    bool m = (g_occ[v] != 0) | (wg >= 0 && (wg & 1));
    __stcs(&out_mask[v], m ? 1.0f : 0.0f);
}

// ---------------- launch ----------------

extern "C" void kernel_launch(void* const* d_in, const int* in_sizes, int n_in,
                              void* d_out, int out_size) {
    const int*   cur_coords = (const int*)d_in[0];
    const float* cur_vals   = (const float*)d_in[1];
    const int*   glb_coords = (const int*)d_in[2];
    const float* glb_vals   = (const float*)d_in[3];
    const int*   ct_coords  = (const int*)d_in[4];
    const float* tsdf_tgt   = (const float*)d_in[5];
    const int*   gct_coords = (const int*)d_in[6];
    const float* gtsdf_tgt  = (const float*)d_in[7];
    const int*   origin     = (const int*)d_in[8];
    const int*   grid_mask  = (const int*)d_in[9];   // bool promoted to 4-byte
    const int*   occupancy  = (const int*)d_in[10];  // bool promoted to 4-byte

    const int n_cur  = in_sizes[0] / 3;
    const int n_glb  = in_sizes[2] / 3;
    const int n_tgt  = in_sizes[4] / 3;
    const int n_gtgt = in_sizes[6] / 3;

    float* out = (float*)d_out;
    // output layout: tuple order, flattened, float32
    float* out_mask  = out;                          // DIM3
    float* out_cur   = out_mask + DIM3;              // DIM3*CH
    float* out_glb   = out_cur + (size_t)DIM3 * CH;  // DIM3*CH
    float* out_tgt   = out_glb + (size_t)DIM3 * CH;  // DIM3
    float* out_valid = out_tgt + DIM3;               // n_glb
    float* out_vt    = out_valid + n_glb;            // n_gtgt
    float* out_near  = out_vt + n_gtgt;              // n_glb

    k_init<<<(DIM3 / 4 + B - 1) / B, B>>>();

    int n_a = n_cur + n_gtgt + n_tgt;
    k_scatter_a<<<(n_a + B - 1) / B, B>>>(cur_coords, grid_mask, occupancy,
                                          gct_coords, ct_coords, origin,
                                          out_vt, n_cur, n_gtgt, n_tgt);

    k_scatter_glb<<<(n_glb + B - 1) / B, B>>>(glb_coords, (const float4*)glb_vals,
                                              origin, out_valid, out_near, n_glb);

    k_fill<<<MISC_BLOCKS + FILL_BLOCKS, B>>>((const float4*)cur_vals, (const float4*)glb_vals,
                                             tsdf_tgt, gtsdf_tgt,
                                             (float4*)out_cur, (float4*)out_glb,
                                             out_tgt, out_mask, n_gtgt);
}

// round 9
// speedup vs baseline: 1.2582x; 1.0303x over previous
#include <cuda_runtime.h>

#define DIM   96
#define DIM3  (DIM * DIM * DIM)   // 884736
#define CH    24
#define CH4   (CH / 4)            // 6 float4 per voxel row
#define FEAT4 (DIM3 * CH4)        // 5308416 float4 elements per volume

#define B         256
#define FILL_ILP  4
#define FILL_THREADS (FEAT4 / FILL_ILP)          // 1327104 (exact)
#define FILL_BLOCKS  (FILL_THREADS / B)          // 5184 (exact)
#define MISC_BLOCKS  (DIM3 / 4 / B)              // 864 (exact, 4 voxels/thread)

// ---------------- scratch (device globals; no allocation allowed) ----------------
// Packed winner pair: .x = win_cur (row or -1), .y = win_glb ((row<<1)|nz or -1)
__device__ int2          g_win_cg[DIM3];
__device__ int           g_win_tgt[DIM3];
__device__ unsigned char g_valid_vol[DIM3];
__device__ unsigned char g_occ[DIM3];

// ---------------- kernels ----------------

// Vectorized scratch reset: winners = -1 (int4), flags = 0.
__global__ void k_init() {
    int i = blockIdx.x * blockDim.x + threadIdx.x;
    const int4 m1 = make_int4(-1, -1, -1, -1);
    if (i < DIM3 / 2)
        ((int4*)g_win_cg)[i] = m1;          // 2 voxels per int4
    if (i < DIM3 / 4) {
        ((int4*)g_win_tgt)[i] = m1;
        ((int*)g_valid_vol)[i] = 0;
        ((int*)g_occ)[i] = 0;
    }
}

// Fused: current-fragment scatter (range [0, n_cur)) and target scatters
// (range [n_cur, n_cur + n_gtgt + n_tgt)). Independent work, one launch.
// atomicMax(row-priority) reproduces XLA's sequential last-write-wins.
__global__ void k_scatter_a(const int* __restrict__ cc,
                            const int* __restrict__ gm,
                            const int* __restrict__ occ,
                            const int* __restrict__ gct,
                            const int* __restrict__ ct,
                            const int* __restrict__ origin,
                            float* __restrict__ out_vt,
                            int n_cur, int n_g, int n_c) {
    int i = blockIdx.x * blockDim.x + threadIdx.x;
    if (i < n_cur) {
        int x = cc[3 * i], y = cc[3 * i + 1], z = cc[3 * i + 2];
        int v = (x * DIM + y) * DIM + z;
        atomicMax(&g_win_cg[v].x, i);
        if (gm[i] != 0)  g_valid_vol[v] = 1;
        if (occ[i] != 0) g_occ[v] = 1;
        return;
    }
    int j = i - n_cur;
    if (j < n_g) {
        // global target rows: scattered first -> lower priority band [0, n_g)
        int x = gct[3 * j]     - origin[0];
        int y = gct[3 * j + 1] - origin[1];
        int z = gct[3 * j + 2] - origin[2];
        bool inb = ((unsigned)x < DIM) && ((unsigned)y < DIM) && ((unsigned)z < DIM);
        out_vt[j] = inb ? 1.0f : 0.0f;
        if (inb) atomicMax(&g_win_tgt[(x * DIM + y) * DIM + z], j);
    } else if (j < n_g + n_c) {
        // current-fragment target rows: scattered second -> win ties
        int t = j - n_g;
        int x = ct[3 * t], y = ct[3 * t + 1], z = ct[3 * t + 2];
        atomicMax(&g_win_tgt[(x * DIM + y) * DIM + z], n_g + t);
    }
}

// Global rows: shift by origin, in-bounds test, gather valid_volume,
// emit `valid`/`near_mask`, record packed winner (row<<1 | row_any_nonzero).
__global__ void k_scatter_glb(const int* __restrict__ gc,
                              const float4* __restrict__ glb_vals,
                              const int* __restrict__ origin,
                              float* __restrict__ out_valid,
                              float* __restrict__ out_near,
                              int n) {
    int i = blockIdx.x * blockDim.x + threadIdx.x;
    if (i >= n) return;
    int x = gc[3 * i]     - origin[0];
    int y = gc[3 * i + 1] - origin[1];
    int z = gc[3 * i + 2] - origin[2];
    bool inb = ((unsigned)x < DIM) && ((unsigned)y < DIM) && ((unsigned)z < DIM);
    bool valid = false;
    if (inb) {
        int v = (x * DIM + y) * DIM + z;
        valid = (g_valid_vol[v] != 0);
        if (valid) {
            bool nz = false;
            #pragma unroll
            for (int q = 0; q < CH4; ++q) {
                float4 r = glb_vals[i * CH4 + q];
                nz |= (r.x != 0.0f) | (r.y != 0.0f) | (r.z != 0.0f) | (r.w != 0.0f);
            }
            atomicMax(&g_win_cg[v].y, (i << 1) | (nz ? 1 : 0));
        }
    }
    out_valid[i] = valid ? 1.0f : 0.0f;
    out_near[i]  = (inb && !valid) ? 1.0f : 0.0f;
}

// Fused dense fill. Misc blocks come FIRST (no ragged tail behind heavy fill
// blocks) and are vectorized 4 voxels/thread. Fill blocks: 4-way ILP over
// grid-strided float4 slices; one LDG.64 fetches both winners per element;
// __stcs streaming stores keep tables/winners L2-resident (output write-once).
__global__ void k_fill(const float4* __restrict__ cur_vals,
                       const float4* __restrict__ glb_vals,
                       const float* __restrict__ tsdf_tgt,
                       const float* __restrict__ gtsdf_tgt,
                       float4* __restrict__ out_cur,
                       float4* __restrict__ out_glb,
                       float4* __restrict__ out_tgt,
                       float4* __restrict__ out_mask,
                       int n_gtgt) {
    int b = blockIdx.x;
    if (b >= MISC_BLOCKS) {
        int base = (b - MISC_BLOCKS) * B + threadIdx.x;
        const float4 zero = make_float4(0.f, 0.f, 0.f, 0.f);
        int e[FILL_ILP];
        int2 w[FILL_ILP];
        #pragma unroll
        for (int k = 0; k < FILL_ILP; ++k) {
            e[k] = base + k * FILL_THREADS;
            w[k] = g_win_cg[e[k] / CH4];
        }
        #pragma unroll
        for (int k = 0; k < FILL_ILP; ++k) {
            int v = e[k] / CH4;
            int q = e[k] - v * CH4;
            float4 rc = (w[k].x >= 0) ? cur_vals[w[k].x * CH4 + q] : zero;
            float4 rg = (w[k].y >= 0) ? glb_vals[(w[k].y >> 1) * CH4 + q] : zero;
            __stcs(&out_cur[e[k]], rc);
            __stcs(&out_glb[e[k]], rg);
        }
        return;
    }
    // misc: 4 voxels per thread; int4 loads cover 2 packed winner pairs each
    int t4 = b * B + threadIdx.x;            // float4 index into out_tgt/out_mask
    int4 wt = ((const int4*)g_win_tgt)[t4];
    int4 wp0 = ((const int4*)g_win_cg)[t4 * 2 + 0];   // voxels v0,v0+1: (cur,glb,cur,glb)
    int4 wp1 = ((const int4*)g_win_cg)[t4 * 2 + 1];   // voxels v0+2,v0+3
    unsigned int occ4 = ((const unsigned int*)g_occ)[t4];

    float tv[4];
    int wts[4] = {wt.x, wt.y, wt.z, wt.w};
    #pragma unroll
    for (int k = 0; k < 4; ++k) {
        int w = wts[k];
        if (w < 0)            tv[k] = 1.0f;
        else if (w >= n_gtgt) tv[k] = tsdf_tgt[w - n_gtgt];
        else                  tv[k] = gtsdf_tgt[w];
    }
    __stcs(&out_tgt[t4], make_float4(tv[0], tv[1], tv[2], tv[3]));

    int wgs[4] = {wp0.y, wp0.w, wp1.y, wp1.w};
    float mv[4];
    #pragma unroll
    for (int k = 0; k < 4; ++k) {
        bool m = ((occ4 >> (8 * k)) & 0xFF) != 0;
        m |= (wgs[k] >= 0) && (wgs[k] & 1);
        mv[k] = m ? 1.0f : 0.0f;
    }
    __stcs(&out_mask[t4], make_float4(mv[0], mv[1], mv[2], mv[3]));
}

// ---------------- launch ----------------

extern "C" void kernel_launch(void* const* d_in, const int* in_sizes, int n_in,
                              void* d_out, int out_size) {
    const int*   cur_coords = (const int*)d_in[0];
    const float* cur_vals   = (const float*)d_in[1];
    const int*   glb_coords = (const int*)d_in[2];
    const float* glb_vals   = (const float*)d_in[3];
    const int*   ct_coords  = (const int*)d_in[4];
    const float* tsdf_tgt   = (const float*)d_in[5];
    const int*   gct_coords = (const int*)d_in[6];
    const float* gtsdf_tgt  = (const float*)d_in[7];
    const int*   origin     = (const int*)d_in[8];
    const int*   grid_mask  = (const int*)d_in[9];   // bool promoted to 4-byte
    const int*   occupancy  = (const int*)d_in[10];  // bool promoted to 4-byte

    const int n_cur  = in_sizes[0] / 3;
    const int n_glb  = in_sizes[2] / 3;
    const int n_tgt  = in_sizes[4] / 3;
    const int n_gtgt = in_sizes[6] / 3;

    float* out = (float*)d_out;
    // output layout: tuple order, flattened, float32
    float* out_mask  = out;                          // DIM3
    float* out_cur   = out_mask + DIM3;              // DIM3*CH
    float* out_glb   = out_cur + (size_t)DIM3 * CH;  // DIM3*CH
    float* out_tgt   = out_glb + (size_t)DIM3 * CH;  // DIM3
    float* out_valid = out_tgt + DIM3;               // n_glb
    float* out_vt    = out_valid + n_glb;            // n_gtgt
    float* out_near  = out_vt + n_gtgt;              // n_glb

    k_init<<<(DIM3 / 2 + B - 1) / B, B>>>();

    int n_a = n_cur + n_gtgt + n_tgt;
    k_scatter_a<<<(n_a + B - 1) / B, B>>>(cur_coords, grid_mask, occupancy,
                                          gct_coords, ct_coords, origin,
                                          out_vt, n_cur, n_gtgt, n_tgt);

    k_scatter_glb<<<(n_glb + B - 1) / B, B>>>(glb_coords, (const float4*)glb_vals,
                                              origin, out_valid, out_near, n_glb);

    k_fill<<<MISC_BLOCKS + FILL_BLOCKS, B>>>((const float4*)cur_vals, (const float4*)glb_vals,
                                             tsdf_tgt, gtsdf_tgt,
                                             (float4*)out_cur, (float4*)out_glb,
                                             (float4*)out_tgt, (float4*)out_mask, n_gtgt);
}